// round 5
// baseline (speedup 1.0000x reference)
#include <cuda_runtime.h>
#include <cstdint>

// Problem constants (from reference)
#define K_BANDS 64
#define C_IN    2
#define O_CH    128
#define T_LEN   1024
#define F_NBINS 1025
#define B_SZ    4
#define TT      16          // t-tile per block
#define W_CAP   256         // upper bound on band width W (actual ~130)
#define XS_STRIDE 20        // (TT + pad) floats; multiple of 4 -> 16B-aligned rows
#define SB_STRIDE 129       // o-dim pad for conflict-free flush reads

// Scratch (no allocations allowed): fused weights mel_w * pre_w, band widths.
__device__ float g_fw[K_BANDS * C_IN * W_CAP * O_CH];
__device__ int   g_n[K_BANDS];
__device__ int   g_idx64;   // 1 if idx buffer is int64, 0 if int32

// packed fp32x2 FMA (Blackwell): doubles fp32 rate vs FFMA-3reg
__device__ __forceinline__ float2 ffma2(float2 a, float2 b, float2 c) {
    float2 d;
    asm("fma.rn.f32x2 %0, %1, %2, %3;"
        : "=l"(*reinterpret_cast<unsigned long long*>(&d))
        : "l"(*reinterpret_cast<const unsigned long long*>(&a)),
          "l"(*reinterpret_cast<const unsigned long long*>(&b)),
          "l"(*reinterpret_cast<const unsigned long long*>(&c)));
    return d;
}

// Detect idx dtype. Band 0's indices are 0,1,2,... so an int32 buffer has
// nonzero odd words (word[1]==1); an int64 LE buffer has zero at every odd
// word (high halves, values < 1025). Scan first 2*W words.
__global__ void prep_detect_idx(const int* __restrict__ idx_raw, int W) {
    int nz_odd = 0;
    for (int i = 1; i < 2 * W; i += 2)
        if (idx_raw[i] != 0) nz_odd++;
    g_idx64 = (nz_odd == 0) ? 1 : 0;
}

// Fold mel weights into pre_w:  g_fw[k,c,w,o] = mel_w[k,w] * pre_w[k,c,w,o]
__global__ void prep_weights(const float* __restrict__ mel_w,
                             const float* __restrict__ pre_w, int W) {
    int total = K_BANDS * C_IN * W * O_CH;
    for (int e = blockIdx.x * blockDim.x + threadIdx.x; e < total;
         e += gridDim.x * blockDim.x) {
        int w = (e >> 7) % W;             // o = e & 127
        int k = e / (O_CH * W * C_IN);
        g_fw[e] = pre_w[e] * mel_w[k * W + w];
    }
}

// Effective width per band (mel_w == 0 on padding)
__global__ void prep_n(const float* __restrict__ mel_w, int W) {
    int k = threadIdx.x;
    if (k >= K_BANDS) return;
    int n = 0;
    for (int w = 0; w < W; w++)
        if (mel_w[k * W + w] != 0.f) n = w + 1;
    g_n[k] = n;
}

// Process one 4-tap weight group against the staged x tile.
__device__ __forceinline__ void fma_group4(const float* __restrict__ xrow0,
                                           float w0, float w1, float w2, float w3,
                                           float2 a[8]) {
    #pragma unroll
    for (int u = 0; u < 4; u++) {
        float wv = (u == 0) ? w0 : (u == 1) ? w1 : (u == 2) ? w2 : w3;
        float2 wv2 = make_float2(wv, wv);
        const float4* xr = (const float4*)(xrow0 + (size_t)u * XS_STRIDE);
        #pragma unroll
        for (int j4 = 0; j4 < 4; j4++) {
            float4 v = xr[j4];   // broadcast LDS.128, 4 t's
            a[2 * j4 + 0] = ffma2(make_float2(v.x, v.y), wv2, a[2 * j4 + 0]);
            a[2 * j4 + 1] = ffma2(make_float2(v.z, v.w), wv2, a[2 * j4 + 1]);
        }
    }
}

// Main kernel: one block per (b, 16-t tile). 128 threads = output channels.
__global__ __launch_bounds__(128)
void band_main(const float* __restrict__ x,
               const void*  __restrict__ idx_raw,
               const float* __restrict__ pre_b,
               float*       __restrict__ out,
               int W) {
    extern __shared__ float sm[];
    float* xs = sm;                                  // [C][W][XS_STRIDE]
    float* sb = sm + (size_t)C_IN * W * XS_STRIDE;   // [TT][8][SB_STRIDE]
    int*   si = (int*)(sb + (size_t)TT * 8 * SB_STRIDE); // [W] band idx cache

    const int tid = threadIdx.x;                     // = o
    const int b   = blockIdx.x % B_SZ;
    const int t0  = (blockIdx.x / B_SZ) * TT;
    const int is64 = g_idx64;

    const float* xb = x + (size_t)b * C_IN * T_LEN * F_NBINS;
    float* ob = out + (size_t)b * O_CH * T_LEN * K_BANDS;

    for (int k = 0; k < K_BANDS; k++) {
        const int n = g_n[k];

        __syncthreads();   // xs/si reads of previous band / sb flush done
        // ---- cache this band's idx slice in SMEM (read 32x below) ----
        if (is64) {
            const long long* ip = (const long long*)idx_raw + (size_t)k * W;
            for (int w = tid; w < n; w += 128) si[w] = (int)ip[w];
        } else {
            const int* ip = (const int*)idx_raw + (size_t)k * W;
            for (int w = tid; w < n; w += 128) si[w] = ip[w];
        }
        __syncthreads();

        // ---- gather x tile for this band into SMEM: xs[c][w][t] ----
        #pragma unroll
        for (int ct = 0; ct < C_IN * TT; ct++) {
            const int c = ct >> 4, t = ct & (TT - 1);
            const float* xrow = xb + ((size_t)c * T_LEN + t0 + t) * F_NBINS;
            for (int w = tid; w < n; w += 128)
                xs[(c * W + w) * XS_STRIDE + t] = xrow[si[w]];
        }
        __syncthreads();

        // ---- accumulate: acc[t] over (c, w<n), weight loads pipelined ----
        float2 a[8];
        #pragma unroll
        for (int j = 0; j < 8; j++) a[j] = make_float2(0.f, 0.f);

        #pragma unroll
        for (int c = 0; c < C_IN; c++) {
            const float* wp = g_fw + ((size_t)(k * C_IN + c) * W) * O_CH + tid;
            const float* xc = xs + (size_t)c * W * XS_STRIDE;
            int w = 0;
            if (n >= 8) {
                // prologue: load group 0
                float w0 = wp[0];
                float w1 = wp[(size_t)1 * O_CH];
                float w2 = wp[(size_t)2 * O_CH];
                float w3 = wp[(size_t)3 * O_CH];
                // steady state: load group g+1 before consuming group g
                for (; w + 8 <= n; w += 4) {
                    float n0 = wp[(size_t)(w + 4) * O_CH];
                    float n1 = wp[(size_t)(w + 5) * O_CH];
                    float n2 = wp[(size_t)(w + 6) * O_CH];
                    float n3 = wp[(size_t)(w + 7) * O_CH];
                    fma_group4(xc + (size_t)w * XS_STRIDE, w0, w1, w2, w3, a);
                    w0 = n0; w1 = n1; w2 = n2; w3 = n3;
                }
                // epilogue: consume last prefetched group
                fma_group4(xc + (size_t)w * XS_STRIDE, w0, w1, w2, w3, a);
                w += 4;
            }
            for (; w < n; w++) {
                float wv = wp[(size_t)w * O_CH];
                float2 wv2 = make_float2(wv, wv);
                const float4* xr = (const float4*)(xc + (size_t)w * XS_STRIDE);
                #pragma unroll
                for (int j4 = 0; j4 < 4; j4++) {
                    float4 v = xr[j4];
                    a[2 * j4 + 0] = ffma2(make_float2(v.x, v.y), wv2, a[2 * j4 + 0]);
                    a[2 * j4 + 1] = ffma2(make_float2(v.z, v.w), wv2, a[2 * j4 + 1]);
                }
            }
        }

        // ---- bias + stage into sb[t][k&7][o] ----
        const float bias = pre_b[k * O_CH + tid];
        const int kk = k & 7;
        #pragma unroll
        for (int j = 0; j < 8; j++) {
            sb[((2 * j + 0) * 8 + kk) * SB_STRIDE + tid] = a[j].x + bias;
            sb[((2 * j + 1) * 8 + kk) * SB_STRIDE + tid] = a[j].y + bias;
        }

        // ---- flush 8-band chunk, lanes sweep k -> full 32B sectors ----
        if (kk == 7) {
            __syncthreads();
            const int k0 = k - 7;
            #pragma unroll
            for (int i = 0; i < (TT * 8 * O_CH) / 128; i++) {  // 128 iters
                int e  = tid + i * 128;
                int kl = e & 7;
                int t  = (e >> 3) & (TT - 1);
                int o  = e >> 7;
                ob[(size_t)o * (T_LEN * K_BANDS) + (size_t)(t0 + t) * K_BANDS
                   + k0 + kl] = sb[(t * 8 + kl) * SB_STRIDE + o];
            }
        }
    }
}

extern "C" void kernel_launch(void* const* d_in, const int* in_sizes, int n_in,
                              void* d_out, int out_size) {
    const float* x     = (const float*)d_in[0];
    const void*  idxr  = d_in[1];
    const float* mel_w = (const float*)d_in[2];
    const float* pre_w = (const float*)d_in[3];
    const float* pre_b = (const float*)d_in[4];
    float* out = (float*)d_out;

    int W = in_sizes[1] / K_BANDS;   // idx has K_BANDS * W elements
    if (W > W_CAP) W = W_CAP;        // safety clamp (never hit: W ~ 130)

    prep_detect_idx<<<1, 1>>>((const int*)idxr, W);
    prep_weights<<<512, 256>>>(mel_w, pre_w, W);
    prep_n<<<1, 64>>>(mel_w, W);

    size_t smem = ((size_t)C_IN * W * XS_STRIDE + (size_t)TT * 8 * SB_STRIDE
                   + W) * sizeof(float);
    cudaFuncSetAttribute(band_main,
                         cudaFuncAttributeMaxDynamicSharedMemorySize,
                         (int)smem);
    band_main<<<B_SZ * (T_LEN / TT), 128, smem>>>(x, idxr, pre_b, out, W);
}

// round 13
// speedup vs baseline: 1.1717x; 1.1717x over previous
#include <cuda_runtime.h>
#include <cstdint>

#define K_BANDS 64
#define C_IN    2
#define O_CH    128
#define T_LEN   1024
#define F_NBINS 1025
#define B_SZ    4
#define TT      16          // t per block
#define KB      8           // bands per block
#define W_CAP   256
#define XS_STRIDE 20        // 16 t + pad, mult of 4 -> float4-aligned rows
#define SB_STRIDE 130       // even (float2 staging), 2-way flush conflict only

__device__ float g_fw[K_BANDS * C_IN * W_CAP * O_CH];
__device__ int   g_n[K_BANDS];
__device__ int   g_idx64;   // 1 if idx buffer is int64, 0 if int32

__device__ __forceinline__ float2 ffma2(float2 a, float2 b, float2 c) {
    float2 d;
    asm("fma.rn.f32x2 %0, %1, %2, %3;"
        : "=l"(*reinterpret_cast<unsigned long long*>(&d))
        : "l"(*reinterpret_cast<const unsigned long long*>(&a)),
          "l"(*reinterpret_cast<const unsigned long long*>(&b)),
          "l"(*reinterpret_cast<const unsigned long long*>(&c)));
    return d;
}

// idx dtype sniffing: band0 indices are 0,1,2,... -> int32 buffer has nonzero
// odd words; int64 LE buffer has all-zero odd (high) words.
__global__ void prep_detect_idx(const int* __restrict__ idx_raw, int W) {
    int nz_odd = 0;
    for (int i = 1; i < 2 * W; i += 2)
        if (idx_raw[i] != 0) nz_odd++;
    g_idx64 = (nz_odd == 0) ? 1 : 0;
}

__global__ void prep_weights(const float* __restrict__ mel_w,
                             const float* __restrict__ pre_w, int W) {
    int total = K_BANDS * C_IN * W * O_CH;
    for (int e = blockIdx.x * blockDim.x + threadIdx.x; e < total;
         e += gridDim.x * blockDim.x) {
        int w = (e >> 7) % W;
        int k = e / (O_CH * W * C_IN);
        g_fw[e] = pre_w[e] * mel_w[k * W + w];
    }
}

__global__ void prep_n(const float* __restrict__ mel_w, int W) {
    int k = threadIdx.x;
    if (k >= K_BANDS) return;
    int n = 0;
    for (int w = 0; w < W; w++)
        if (mel_w[k * W + w] != 0.f) n = w + 1;
    g_n[k] = n;
}

// 8 taps: weights wv[8] (float2 over o-pair), x rows from xs (float4 over t).
__device__ __forceinline__ void fma_tap8(const float* __restrict__ xrow0,
                                         const float2* wv,
                                         float2 aA[4], float2 aB[4]) {
    #pragma unroll
    for (int u = 0; u < 8; u++) {
        const float4* xr = (const float4*)(xrow0 + (size_t)u * XS_STRIDE);
        float4 v0 = xr[0], v1 = xr[1];             // 8 t's, LDS.128 broadcast
        float2 wa = make_float2(wv[u].x, wv[u].x);
        float2 wb = make_float2(wv[u].y, wv[u].y);
        aA[0] = ffma2(make_float2(v0.x, v0.y), wa, aA[0]);
        aA[1] = ffma2(make_float2(v0.z, v0.w), wa, aA[1]);
        aA[2] = ffma2(make_float2(v1.x, v1.y), wa, aA[2]);
        aA[3] = ffma2(make_float2(v1.z, v1.w), wa, aA[3]);
        aB[0] = ffma2(make_float2(v0.x, v0.y), wb, aB[0]);
        aB[1] = ffma2(make_float2(v0.z, v0.w), wb, aB[1]);
        aB[2] = ffma2(make_float2(v1.x, v1.y), wb, aB[2]);
        aB[3] = ffma2(make_float2(v1.z, v1.w), wb, aB[3]);
    }
}

// One block = (b, 16-t tile, 8-band group). 128 threads:
//   op = tid&63 -> o-pair (o0 = 2*op), th = tid>>6 -> t-half (8 t's).
__global__ __launch_bounds__(128)
void band_main(const float* __restrict__ x,
               const void*  __restrict__ idx_raw,
               const float* __restrict__ pre_b,
               float*       __restrict__ out,
               int W) {
    extern __shared__ float sm[];
    float* xs = sm;                                  // [C][W][XS_STRIDE]
    float* sb = sm + (size_t)C_IN * W * XS_STRIDE;   // [TT][KB][SB_STRIDE]

    const int tid = threadIdx.x;
    const int bi  = blockIdx.x;
    const int kg  = bi & 7;            // band group (fastest-varying for balance)
    const int bt  = bi >> 3;           // 0..255
    const int b   = bt & 3;
    const int t0  = (bt >> 2) * TT;

    const int op = tid & 63, o0 = op * 2, th = tid >> 6;
    const int is64 = g_idx64;

    const float* xb = x + (size_t)b * C_IN * T_LEN * F_NBINS;
    float* ob = out + (size_t)b * O_CH * T_LEN * K_BANDS;

    for (int kk = 0; kk < KB; kk++) {
        const int k = kg * KB + kk;
        const int n = g_n[k];

        __syncthreads();   // previous band's xs reads complete
        // ---- gather x tile: xs[c][w][t], idx read directly (L1-hot) ----
        if (is64) {
            const long long* ip = (const long long*)idx_raw + (size_t)k * W;
            #pragma unroll
            for (int ct = 0; ct < C_IN * TT; ct++) {
                const int c = ct >> 4, t = ct & (TT - 1);
                const float* xrow = xb + ((size_t)c * T_LEN + t0 + t) * F_NBINS;
                for (int w = tid; w < n; w += 128)
                    xs[(c * W + w) * XS_STRIDE + t] = xrow[(int)ip[w]];
            }
        } else {
            const int* ip = (const int*)idx_raw + (size_t)k * W;
            #pragma unroll
            for (int ct = 0; ct < C_IN * TT; ct++) {
                const int c = ct >> 4, t = ct & (TT - 1);
                const float* xrow = xb + ((size_t)c * T_LEN + t0 + t) * F_NBINS;
                for (int w = tid; w < n; w += 128)
                    xs[(c * W + w) * XS_STRIDE + t] = xrow[ip[w]];
            }
        }
        __syncthreads();

        // ---- accumulate: 2 o-channels x 8 t's per thread ----
        float2 aA[4], aB[4];
        #pragma unroll
        for (int j = 0; j < 4; j++) { aA[j] = make_float2(0.f, 0.f);
                                      aB[j] = make_float2(0.f, 0.f); }

        #pragma unroll
        for (int c = 0; c < C_IN; c++) {
            // weights as float2 over the o-pair; one tap = 64 float2
            const float2* wq = (const float2*)(g_fw +
                               ((size_t)(k * C_IN + c) * W) * O_CH) + op;
            const float* xc = xs + (size_t)c * W * XS_STRIDE + th * 8;
            int w = 0;
            if (n >= 16) {
                float2 cur[8], nxt[8];
                #pragma unroll
                for (int u = 0; u < 8; u++) cur[u] = wq[(size_t)u * 64];
                for (; w + 16 <= n; w += 8) {
                    #pragma unroll
                    for (int u = 0; u < 8; u++)
                        nxt[u] = wq[(size_t)(w + 8 + u) * 64];
                    fma_tap8(xc + (size_t)w * XS_STRIDE, cur, aA, aB);
                    #pragma unroll
                    for (int u = 0; u < 8; u++) cur[u] = nxt[u];
                }
                fma_tap8(xc + (size_t)w * XS_STRIDE, cur, aA, aB);
                w += 8;
            }
            for (; w < n; w++) {   // tail < 8 taps
                float2 wv = wq[(size_t)w * 64];
                const float4* xr = (const float4*)(xc + (size_t)w * XS_STRIDE);
                float4 v0 = xr[0], v1 = xr[1];
                float2 wa = make_float2(wv.x, wv.x);
                float2 wb = make_float2(wv.y, wv.y);
                aA[0] = ffma2(make_float2(v0.x, v0.y), wa, aA[0]);
                aA[1] = ffma2(make_float2(v0.z, v0.w), wa, aA[1]);
                aA[2] = ffma2(make_float2(v1.x, v1.y), wa, aA[2]);
                aA[3] = ffma2(make_float2(v1.z, v1.w), wa, aA[3]);
                aB[0] = ffma2(make_float2(v0.x, v0.y), wb, aB[0]);
                aB[1] = ffma2(make_float2(v0.z, v0.w), wb, aB[1]);
                aB[2] = ffma2(make_float2(v1.x, v1.y), wb, aB[2]);
                aB[3] = ffma2(make_float2(v1.z, v1.w), wb, aB[3]);
            }
        }

        // ---- bias + stage: sb[t][kk][o] (disjoint per band, no race) ----
        float2 bias = ((const float2*)(pre_b + (size_t)k * O_CH))[op];
        #pragma unroll
        for (int j = 0; j < 4; j++) {
            #pragma unroll
            for (int h = 0; h < 2; h++) {
                int t = th * 8 + 2 * j + h;
                float va = (h ? aA[j].y : aA[j].x) + bias.x;
                float vb = (h ? aB[j].y : aB[j].x) + bias.y;
                *(float2*)&sb[(t * KB + kk) * SB_STRIDE + o0] =
                    make_float2(va, vb);
            }
        }
    }

    // ---- flush: lanes sweep k -> full 32B sectors ----
    __syncthreads();
    #pragma unroll 4
    for (int i = 0; i < (TT * KB * O_CH) / 128; i++) {   // 128 iters
        int e  = tid + i * 128;
        int kl = e & 7;
        int t  = (e >> 3) & (TT - 1);
        int o  = e >> 7;
        ob[(size_t)o * (T_LEN * K_BANDS) + (size_t)(t0 + t) * K_BANDS
           + kg * KB + kl] = sb[(t * KB + kl) * SB_STRIDE + o];
    }
}

extern "C" void kernel_launch(void* const* d_in, const int* in_sizes, int n_in,
                              void* d_out, int out_size) {
    const float* x     = (const float*)d_in[0];
    const void*  idxr  = d_in[1];
    const float* mel_w = (const float*)d_in[2];
    const float* pre_w = (const float*)d_in[3];
    const float* pre_b = (const float*)d_in[4];
    float* out = (float*)d_out;

    int W = in_sizes[1] / K_BANDS;
    if (W > W_CAP) W = W_CAP;

    prep_detect_idx<<<1, 1>>>((const int*)idxr, W);
    prep_weights<<<512, 256>>>(mel_w, pre_w, W);
    prep_n<<<1, 64>>>(mel_w, W);

    size_t smem = ((size_t)C_IN * W * XS_STRIDE
                   + (size_t)TT * KB * SB_STRIDE) * sizeof(float);
    cudaFuncSetAttribute(band_main,
                         cudaFuncAttributeMaxDynamicSharedMemorySize,
                         (int)smem);
    band_main<<<B_SZ * (T_LEN / TT) * (K_BANDS / KB), 128, smem>>>(
        x, idxr, pre_b, out, W);
}